// round 2
// baseline (speedup 1.0000x reference)
#include <cuda_runtime.h>
#include <cuda_bf16.h>

// Subtraction: out[n,c,k,l] = x[n,c,oh,ow] - xpad[n,c,oh+i,ow+j]
// K=7, PAD=3, STRIDE=1, DIL=1, x:(16,64,56,56) f32 -> out:(16,64,49,3136) f32
//
// One CTA per (n,c) plane. Plane staged in a 62x62 zero-padded SMEM tile.
// 224 threads = 4 rows x 56 cols; 14 row-iterations cover oh=0..55.
// Inner 7x7 loop fully unrolled with constant offsets; stores are contiguous
// in l per k -> perfectly coalesced. Kernel is HBM-write-bound (~629 MB out).

#define PLANE 3136          // 56*56
#define TPITCH 62           // 56 + 2*3
#define NTHREADS 224        // 4 rows * 56 cols

__global__ __launch_bounds__(NTHREADS, 1)
void Subtraction_68212670595965_kernel(const float* __restrict__ x,
                                       float* __restrict__ out) {
    __shared__ float tile[TPITCH * TPITCH];   // 62*62*4 = 15376 B

    const int nc  = blockIdx.x;               // 0..1023  (n*64 + c)
    const float* __restrict__ xin = x + (size_t)nc * PLANE;
    float* __restrict__ outb = out + (size_t)nc * 49 * PLANE;

    const int tid = threadIdx.x;

    // Stage padded plane: tile[r][c] = x[r-3][c-3] for interior, 0 on 3-wide halo.
    #pragma unroll 1
    for (int idx = tid; idx < TPITCH * TPITCH; idx += NTHREADS) {
        const int r = idx / TPITCH;
        const int c = idx - r * TPITCH;
        float v = 0.0f;
        if (r >= 3 && r < 59 && c >= 3 && c < 59)
            v = xin[(r - 3) * 56 + (c - 3)];
        tile[idx] = v;
    }
    __syncthreads();

    const int ow  = tid % 56;     // column this thread owns
    const int oh0 = tid / 56;     // 0..3

    #pragma unroll 1
    for (int rr = 0; rr < 14; ++rr) {
        const int oh = oh0 + rr * 4;
        const int p0 = oh * TPITCH + ow;                 // (i=0,j=0) patch addr
        const float center = tile[p0 + 3 * TPITCH + 3];  // x[oh][ow]
        float* __restrict__ op = outb + oh * 56 + ow;    // l = oh*56+ow

        #pragma unroll
        for (int i = 0; i < 7; ++i) {
            #pragma unroll
            for (int j = 0; j < 7; ++j) {
                op[(i * 7 + j) * PLANE] = center - tile[p0 + i * TPITCH + j];
            }
        }
    }
}

extern "C" void kernel_launch(void* const* d_in, const int* in_sizes, int n_in,
                              void* d_out, int out_size) {
    const float* x = (const float*)d_in[0];
    float* out = (float*)d_out;
    // 16 * 64 = 1024 (n,c) planes
    Subtraction_68212670595965_kernel<<<1024, NTHREADS>>>(x, out);
}

// round 3
// speedup vs baseline: 1.1372x; 1.1372x over previous
#include <cuda_runtime.h>
#include <cuda_bf16.h>

// out[n,c,k,l] = x[n,c,oh,ow] - xpad[n,c,oh+i,ow+j]; K=7, PAD=3
// x:(16,64,56,56) f32 -> out:(16,64,49,3136) f32. HBM-write-bound (~629MB out).
//
// R2: float4 streaming stores (st.global.cs.v4), SMEM pitch 64 for LDS.128 row
// loads, 256 threads. Each thread handles a group of 4 consecutive l per k.

#define PLANE   3136        // 56*56
#define TPITCH  64          // padded pitch (16B-aligned rows)
#define TROWS   62          // 56 + 2*3
#define NTHREADS 256
#define NGROUPS 784         // 3136 / 4 float4-groups per k

__global__ __launch_bounds__(NTHREADS, 1)
void Subtraction_68212670595965_kernel(const float* __restrict__ x,
                                       float* __restrict__ out) {
    __shared__ float tile[TROWS * TPITCH];   // 62*64*4 = 15872 B

    const int nc = blockIdx.x;               // n*64 + c, 0..1023
    const float* __restrict__ xin = x + (size_t)nc * PLANE;
    float* __restrict__ outb = out + (size_t)nc * 49 * PLANE;

    const int tid = threadIdx.x;

    // Stage padded plane (zero halo + zero cols 62..63 of the pitch).
    #pragma unroll 1
    for (int idx = tid; idx < TROWS * TPITCH; idx += NTHREADS) {
        const int r = idx >> 6;        // /64
        const int c = idx & 63;
        float v = 0.0f;
        if (r >= 3 && r < 59 && c >= 3 && c < 59)
            v = xin[(r - 3) * 56 + (c - 3)];
        tile[idx] = v;
    }
    __syncthreads();

    // Groups of 4 consecutive l. 784 groups; 14 groups per output row.
    #pragma unroll 1
    for (int g = tid; g < NGROUPS; g += NTHREADS) {
        const int oh  = g / 14;
        const int ow4 = (g - oh * 14) * 4;          // 0,4,...,52

        // centers: x[oh][ow4..ow4+3] = tile[(oh+3)*64 + ow4+3 .. +6]
        const int cbase = (oh + 3) * TPITCH + ow4 + 3;
        const float c0 = tile[cbase + 0];
        const float c1 = tile[cbase + 1];
        const float c2 = tile[cbase + 2];
        const float c3 = tile[cbase + 3];

        float* __restrict__ op = outb + 4 * g;

        #pragma unroll
        for (int i = 0; i < 7; ++i) {
            const float4* rp =
                reinterpret_cast<const float4*>(&tile[(oh + i) * TPITCH + ow4]);
            const float4 a = rp[0];
            const float4 b = rp[1];
            const float4 cq = rp[2];
            const float r[12] = {a.x, a.y, a.z, a.w,
                                 b.x, b.y, b.z, b.w,
                                 cq.x, cq.y, cq.z, cq.w};
            #pragma unroll
            for (int j = 0; j < 7; ++j) {
                float4 o;
                o.x = c0 - r[j + 0];
                o.y = c1 - r[j + 1];
                o.z = c2 - r[j + 2];
                o.w = c3 - r[j + 3];
                __stcs(reinterpret_cast<float4*>(op + (i * 7 + j) * PLANE), o);
            }
        }
    }
}

extern "C" void kernel_launch(void* const* d_in, const int* in_sizes, int n_in,
                              void* d_out, int out_size) {
    const float* x = (const float*)d_in[0];
    float* out = (float*)d_out;
    Subtraction_68212670595965_kernel<<<1024, NTHREADS>>>(x, out);
}